// round 2
// baseline (speedup 1.0000x reference)
#include <cuda_runtime.h>
#include <cstdint>

// ---------------- problem constants ----------------
#define N_NODES 30000
#define N_EDGES 480000
#define T_STEPS 8
#define F_IN    8
#define HID     32
#define KCHEB   5
#define PERIODS 8

#define KH   (KCHEB*HID)    // 160 hidden-cheb columns
#define KX   (KCHEB*F_IN)   // 40 input-cheb columns
#define KTOT (KH+KX)        // 200
#define GATES 128           // 4*HID
#define TF   (T_STEPS*F_IN) // 64

#define NODES_PER_BLK 128
#define ASTR (KTOT+1)       // 201, conflict-free smem stride
#define SMEM_BYTES ((KTOT*GATES + NODES_PER_BLK*ASTR)*4)

// ---------------- device scratch (static, allocation-free) ----------------
__device__ int   g_deg[N_NODES];
__device__ int   g_counts[N_NODES];
__device__ int   g_cursor[N_NODES];
__device__ float g_dis[N_NODES];
__device__ int   g_rowptr[N_NODES+1];
__device__ int   g_col[N_EDGES];
__device__ float g_val[N_EDGES];
__device__ float g_XT[(size_t)KCHEB*N_NODES*TF];   // cheb planes of inputs, [k][n][t*8+f]
__device__ float g_Hcheb[(size_t)N_NODES*KH];      // [n][k*32+h]; cols 0:32 hold H
__device__ float g_C[(size_t)N_NODES*HID];
__device__ float g_Wcat[KTOT*GATES];               // flattened [200][128] gate weights

// ---------------- helpers ----------------
__device__ __forceinline__ float sigmoidf_(float x){ return 1.f/(1.f+__expf(-x)); }
__device__ __forceinline__ float tanhf_(float x){ return 2.f/(1.f+__expf(-2.f*x)) - 1.f; }

__device__ __forceinline__ unsigned long long bcast2(float a){
    unsigned long long r;
    asm("mov.b64 %0, {%1, %1};" : "=l"(r) : "r"(__float_as_uint(a)));
    return r;
}
__device__ __forceinline__ void fma2(unsigned long long &d, unsigned long long a, unsigned long long b){
    asm("fma.rn.f32x2 %0, %1, %2, %0;" : "+l"(d) : "l"(a), "l"(b));
}

// ---------------- setup kernels ----------------
__global__ void zero_init_kernel(){
    int i = blockIdx.x*blockDim.x + threadIdx.x;
    if (i < N_NODES) { g_deg[i] = 0; g_counts[i] = 0; g_cursor[i] = 0; }
    if (i < N_NODES*HID) {
        g_C[i] = 0.f;
        int n = i >> 5, h = i & 31;
        g_Hcheb[(size_t)n*KH + h] = 0.f;
    }
}

__global__ void prep_weights_kernel(const float* __restrict__ Wx, const float* __restrict__ Wh){
    int i = blockIdx.x*blockDim.x + threadIdx.x;
    if (i >= KTOT*GATES) return;
    int row = i / GATES, colc = i - row*GATES;
    int g = colc >> 5, h = colc & 31;
    float v;
    if (row < KH) {
        int k = row >> 5, ii = row & 31;
        v = Wh[((g*KCHEB + k)*HID + ii)*HID + h];     // Wh[g][k][ii][h]
    } else {
        int r = row - KH;
        int k = r >> 3, f = r & 7;
        v = Wx[((g*KCHEB + k)*F_IN + f)*HID + h];     // Wx[g][k][f][h]
    }
    g_Wcat[i] = v;
}

__global__ void transpose_x_kernel(const float* __restrict__ ts){
    int i = blockIdx.x*blockDim.x + threadIdx.x;
    if (i >= N_NODES*TF) return;
    int n = i / TF, r = i - n*TF;
    int t = r >> 3, f = r & 7;
    g_XT[i] = ts[((size_t)t*N_NODES + n)*F_IN + f];   // plane 0 = T0 = x, node-major
}

__global__ void edge_deg_count_kernel(const int* __restrict__ ei){
    int e = blockIdx.x*blockDim.x + threadIdx.x;
    if (e >= N_EDGES) return;
    int s = ei[e], d = ei[N_EDGES + e];
    if (s != d) atomicAdd(&g_deg[s], 1);
    atomicAdd(&g_counts[d], 1);
}

__global__ void compute_dis_kernel(){
    int i = blockIdx.x*blockDim.x + threadIdx.x;
    if (i >= N_NODES) return;
    int d = g_deg[i];
    g_dis[i] = (d > 0) ? rsqrtf((float)d) : 0.f;
}

__global__ void scan_kernel(){
    __shared__ int sh[1024];
    __shared__ int s_carry;
    int t = threadIdx.x;
    if (t == 0) s_carry = 0;
    __syncthreads();
    for (int base = 0; base < N_NODES; base += 1024) {
        int i = base + t;
        int v = (i < N_NODES) ? g_counts[i] : 0;
        sh[t] = v;
        __syncthreads();
        for (int off = 1; off < 1024; off <<= 1) {
            int x = (t >= off) ? sh[t - off] : 0;
            __syncthreads();
            sh[t] += x;
            __syncthreads();
        }
        int carry = s_carry;
        if (i < N_NODES) g_rowptr[i] = carry + sh[t] - v;
        __syncthreads();
        if (t == 1023) s_carry = carry + sh[1023];
        __syncthreads();
    }
    if (t == 0) g_rowptr[N_NODES] = s_carry;
}

__global__ void scatter_edges_kernel(const int* __restrict__ ei){
    int e = blockIdx.x*blockDim.x + threadIdx.x;
    if (e >= N_EDGES) return;
    int s = ei[e], d = ei[N_EDGES + e];
    int pos = g_rowptr[d] + atomicAdd(&g_cursor[d], 1);
    g_col[pos] = s;
    g_val[pos] = (s == d) ? 0.f : -g_dis[s]*g_dis[d];  // minus of lap folded in
}

// ---------------- Chebyshev step: out = a * Lhat(in) - sub ----------------
// warp per node, lane per channel; grid.y selects 32-channel segment
__global__ void cheb_step_kernel(const float* __restrict__ in, const float* __restrict__ sub,
                                 float* __restrict__ out, int stride, float a)
{
    int node = (blockIdx.x * blockDim.x + threadIdx.x) >> 5;
    if (node >= N_NODES) return;
    int c = (blockIdx.y << 5) + (threadIdx.x & 31);
    int beg = g_rowptr[node], end = g_rowptr[node+1];
    float acc = 0.f;
    for (int e = beg; e < end; ++e) {
        int s = g_col[e];
        float v = g_val[e];
        acc += v * __ldg(&in[(size_t)s*stride + c]);
    }
    size_t idx = (size_t)node*stride + c;
    float r = a * acc;
    if (sub) r -= sub[idx];
    out[idx] = r;
}

// ---------------- fused gate GEMM [N,200]x[200,128] + LSTM pointwise ----------------
__global__ void __launch_bounds__(512, 1) lstm_step_kernel(
    const float* __restrict__ w_c, const float* __restrict__ b_gates, int t)
{
    extern __shared__ float sm[];
    float* Wsm = sm;                     // 200*128 floats
    float* Asm = sm + KTOT*GATES;        // 128*201 floats
    int tid = threadIdx.x;
    int nodeBase = blockIdx.x * NODES_PER_BLK;

    for (int i = tid; i < KTOT*GATES; i += 512) Wsm[i] = g_Wcat[i];
    for (int i = tid; i < NODES_PER_BLK*KH; i += 512) {
        int nl = i / KH, kk = i - nl*KH;
        int node = nodeBase + nl;
        Asm[nl*ASTR + kk] = (node < N_NODES) ? g_Hcheb[(size_t)node*KH + kk] : 0.f;
    }
    for (int i = tid; i < NODES_PER_BLK*KX; i += 512) {
        int nl = i / KX, j = i - nl*KX;
        int k = j >> 3, f = j & 7;
        int node = nodeBase + nl;
        Asm[nl*ASTR + KH + j] = (node < N_NODES)
            ? g_XT[(size_t)k*((size_t)N_NODES*TF) + (size_t)node*TF + t*F_IN + f] : 0.f;
    }
    __syncthreads();

    int q  = tid >> 7;      // gate slice 0..3 (same across a warp -> broadcast weight LDS)
    int nl = tid & 127;     // node within block
    unsigned long long acc[16];
#pragma unroll
    for (int j = 0; j < 16; ++j) acc[j] = 0ull;
    const float* arow = &Asm[nl*ASTR];
#pragma unroll 2
    for (int kk = 0; kk < KTOT; ++kk) {
        unsigned long long aa = bcast2(arow[kk]);
        const ulonglong2* w4 = (const ulonglong2*)&Wsm[kk*GATES + q*32];
#pragma unroll
        for (int j = 0; j < 8; ++j) {
            ulonglong2 w = w4[j];
            fma2(acc[2*j],   aa, w.x);
            fma2(acc[2*j+1], aa, w.y);
        }
    }
    __syncthreads();            // Asm free; reuse as gate buffer (stride 129)
    float* Gsm = Asm;
#pragma unroll
    for (int j = 0; j < 16; ++j) {
        unsigned int lo = (unsigned int)acc[j];
        unsigned int hi = (unsigned int)(acc[j] >> 32);
        Gsm[nl*129 + q*32 + 2*j]     = __uint_as_float(lo);
        Gsm[nl*129 + q*32 + 2*j + 1] = __uint_as_float(hi);
    }
    __syncthreads();

    for (int idx = tid; idx < NODES_PER_BLK*HID; idx += 512) {
        int nl2 = idx >> 5, h = idx & 31;
        int node = nodeBase + nl2;
        if (node >= N_NODES) continue;
        float Cold = g_C[(size_t)node*HID + h];
        const float* grow = &Gsm[nl2*129];
        float gi = grow[h]      + w_c[h]      * Cold + b_gates[h];
        float gf = grow[32 + h] + w_c[32 + h] * Cold + b_gates[32 + h];
        float gc = grow[64 + h]                      + b_gates[64 + h];
        float go = grow[96 + h]                      + b_gates[96 + h];
        float I  = sigmoidf_(gi);
        float F  = sigmoidf_(gf);
        float Tg = tanhf_(gc);
        float Cn = F * Cold + I * Tg;
        float O  = sigmoidf_(go + w_c[64 + h] * Cn);
        g_C[(size_t)node*HID + h] = Cn;
        g_Hcheb[(size_t)node*KH + h] = O * tanhf_(Cn);   // new H into cheb col 0
    }
}

// ---------------- final: out = relu(H) @ W_lin^T + b_lin ----------------
__global__ void final_out_kernel(const float* __restrict__ W_lin, const float* __restrict__ b_lin,
                                 float* __restrict__ out)
{
    int i = blockIdx.x*blockDim.x + threadIdx.x;
    if (i >= N_NODES*PERIODS) return;
    int n = i >> 3, p = i & 7;
    float s = b_lin[p];
    const float* hrow = &g_Hcheb[(size_t)n*KH];
    const float* wrow = &W_lin[p*HID];
#pragma unroll
    for (int h = 0; h < HID; ++h) s += fmaxf(hrow[h], 0.f) * wrow[h];
    out[i] = s;
}

// ---------------- launch ----------------
extern "C" void kernel_launch(void* const* d_in, const int* in_sizes, int n_in,
                              void* d_out, int out_size)
{
    const float* timesteps  = (const float*)d_in[0];
    const int*   edge_index = (const int*)  d_in[1];
    const float* Wx         = (const float*)d_in[2];
    const float* Wh         = (const float*)d_in[3];
    const float* w_c        = (const float*)d_in[4];
    const float* b_gates    = (const float*)d_in[5];
    const float* W_lin      = (const float*)d_in[6];
    const float* b_lin      = (const float*)d_in[7];
    float* out = (float*)d_out;

    cudaFuncSetAttribute(lstm_step_kernel,
                         cudaFuncAttributeMaxDynamicSharedMemorySize, SMEM_BYTES);

    void* p;
    cudaGetSymbolAddress(&p, g_XT);    float* XT    = (float*)p;
    cudaGetSymbolAddress(&p, g_Hcheb); float* Hcheb = (float*)p;

    zero_init_kernel   <<<(N_NODES*HID + 255)/256, 256>>>();
    prep_weights_kernel<<<(KTOT*GATES + 255)/256, 256>>>(Wx, Wh);
    transpose_x_kernel <<<(N_NODES*TF + 255)/256, 256>>>(timesteps);
    edge_deg_count_kernel<<<(N_EDGES + 255)/256, 256>>>(edge_index);
    compute_dis_kernel <<<(N_NODES + 255)/256, 256>>>();
    scan_kernel        <<<1, 1024>>>();
    scatter_edges_kernel<<<(N_EDGES + 255)/256, 256>>>(edge_index);

    const size_t plane = (size_t)N_NODES*TF;
    dim3 chebGrid2((N_NODES + 7)/8, 2);   // C=64 (all timesteps batched)
    dim3 chebGrid1((N_NODES + 7)/8, 1);   // C=32

    // Chebyshev planes of the inputs: T1..T4 over [N, 64]
    for (int k = 1; k < KCHEB; ++k) {
        cheb_step_kernel<<<chebGrid2, 256>>>(
            XT + (size_t)(k-1)*plane,
            (k >= 2) ? XT + (size_t)(k-2)*plane : nullptr,
            XT + (size_t)k*plane,
            TF, (k == 1) ? 1.f : 2.f);
    }

    const int nblk = (N_NODES + NODES_PER_BLK - 1)/NODES_PER_BLK;
    for (int t = 0; t < T_STEPS; ++t) {
        for (int k = 1; k < KCHEB; ++k) {
            cheb_step_kernel<<<chebGrid1, 256>>>(
                Hcheb + 32*(k-1),
                (k >= 2) ? Hcheb + 32*(k-2) : nullptr,
                Hcheb + 32*k,
                KH, (k == 1) ? 1.f : 2.f);
        }
        lstm_step_kernel<<<nblk, 512, SMEM_BYTES>>>(w_c, b_gates, t);
    }

    final_out_kernel<<<(N_NODES*PERIODS + 255)/256, 256>>>(W_lin, b_lin, out);
}

// round 7
// speedup vs baseline: 1.0542x; 1.0542x over previous
#include <cuda_runtime.h>
#include <cstdint>

// ---------------- problem constants ----------------
#define N_NODES 30000
#define N_EDGES 480000
#define T_STEPS 8
#define F_IN    8
#define HID     32
#define KCHEB   5
#define PERIODS 8

#define KH   (KCHEB*HID)    // 160 hidden-cheb columns
#define KX   (KCHEB*F_IN)   // 40 input-cheb columns
#define KTOT (KH+KX)        // 200
#define GATES 128           // 4*HID
#define TF   (T_STEPS*F_IN) // 64

#define NODES_PER_BLK 128
#define ASTR (KTOT+1)       // 201, conflict-free smem stride
#define SMEM_BYTES ((KTOT*GATES + NODES_PER_BLK*ASTR)*4)

// ---------------- device scratch (static, allocation-free) ----------------
__device__ int   g_deg[N_NODES];
__device__ int   g_counts[N_NODES];
__device__ int   g_cursor[N_NODES];
__device__ float g_dis[N_NODES];
__device__ int   g_rowptr[N_NODES+1];
__device__ int   g_col[N_EDGES];
__device__ float g_val[N_EDGES];
__device__ float g_XT[(size_t)KCHEB*N_NODES*TF];   // cheb planes of inputs, [k][n][t*8+f]
__device__ float g_Hcheb[(size_t)N_NODES*KH];      // [n][k*32+h]; cols 0:32 hold H
__device__ float g_C[(size_t)N_NODES*HID];
__device__ float g_Wcat[KTOT*GATES];               // flattened [200][128] gate weights

// ---------------- helpers ----------------
__device__ __forceinline__ float sigmoidf_(float x){ return 1.f/(1.f+__expf(-x)); }
__device__ __forceinline__ float tanhf_(float x){ return 2.f/(1.f+__expf(-2.f*x)) - 1.f; }

__device__ __forceinline__ unsigned long long bcast2(float a){
    unsigned long long r;
    asm("mov.b64 %0, {%1, %1};" : "=l"(r) : "r"(__float_as_uint(a)));
    return r;
}
__device__ __forceinline__ void fma2(unsigned long long &d, unsigned long long a, unsigned long long b){
    asm("fma.rn.f32x2 %0, %1, %2, %0;" : "+l"(d) : "l"(a), "l"(b));
}

// ---------------- fused setup: zero + weight flatten + input transpose ----------------
__global__ void init_kernel(const float* __restrict__ ts,
                            const float* __restrict__ Wx, const float* __restrict__ Wh){
    int i = blockIdx.x*blockDim.x + threadIdx.x;
    if (i < N_NODES) { g_deg[i] = 0; g_counts[i] = 0; g_cursor[i] = 0; }
    if (i < N_NODES*HID) g_C[i] = 0.f;
    if (i < N_NODES*KH) g_Hcheb[i] = 0.f;   // all 5 cheb planes of H zeroed (H0 = 0)
    if (i < KTOT*GATES) {
        int row = i / GATES, colc = i - row*GATES;
        int g = colc >> 5, h = colc & 31;
        float v;
        if (row < KH) {
            int k = row >> 5, ii = row & 31;
            v = Wh[((g*KCHEB + k)*HID + ii)*HID + h];
        } else {
            int r = row - KH;
            int k = r >> 3, f = r & 7;
            v = Wx[((g*KCHEB + k)*F_IN + f)*HID + h];
        }
        g_Wcat[i] = v;
    }
    if (i < N_NODES*TF) {
        int n = i / TF, r = i - n*TF;
        int t = r >> 3, f = r & 7;
        g_XT[i] = ts[((size_t)t*N_NODES + n)*F_IN + f];
    }
}

__global__ void edge_deg_count_kernel(const int* __restrict__ ei){
    int e = blockIdx.x*blockDim.x + threadIdx.x;
    if (e >= N_EDGES) return;
    int s = ei[e], d = ei[N_EDGES + e];
    if (s != d) atomicAdd(&g_deg[s], 1);
    atomicAdd(&g_counts[d], 1);
}

__global__ void compute_dis_kernel(){
    int i = blockIdx.x*blockDim.x + threadIdx.x;
    if (i >= N_NODES) return;
    int d = g_deg[i];
    g_dis[i] = (d > 0) ? rsqrtf((float)d) : 0.f;
}

__global__ void scan_kernel(){
    __shared__ int sh[1024];
    __shared__ int s_carry;
    int t = threadIdx.x;
    if (t == 0) s_carry = 0;
    __syncthreads();
    for (int base = 0; base < N_NODES; base += 1024) {
        int i = base + t;
        int v = (i < N_NODES) ? g_counts[i] : 0;
        sh[t] = v;
        __syncthreads();
        for (int off = 1; off < 1024; off <<= 1) {
            int x = (t >= off) ? sh[t - off] : 0;
            __syncthreads();
            sh[t] += x;
            __syncthreads();
        }
        int carry = s_carry;
        if (i < N_NODES) g_rowptr[i] = carry + sh[t] - v;
        __syncthreads();
        if (t == 1023) s_carry = carry + sh[1023];
        __syncthreads();
    }
    if (t == 0) g_rowptr[N_NODES] = s_carry;
}

__global__ void scatter_edges_kernel(const int* __restrict__ ei){
    int e = blockIdx.x*blockDim.x + threadIdx.x;
    if (e >= N_EDGES) return;
    int s = ei[e], d = ei[N_EDGES + e];
    int pos = g_rowptr[d] + atomicAdd(&g_cursor[d], 1);
    g_col[pos] = s;
    g_val[pos] = (s == d) ? 0.f : -g_dis[s]*g_dis[d];  // minus of lap folded in
}

// ---------------- Chebyshev step: out = a * Lhat(in) - sub ----------------
// warp per node, lane per channel; grid.y selects 32-channel segment.
// Manually unrolled x8 to maximize gather MLP (L2-latency hiding).
__global__ void __launch_bounds__(256) cheb_step_kernel(
    const float* __restrict__ in, const float* __restrict__ sub,
    float* __restrict__ out, int stride, float a)
{
    int node = (blockIdx.x * blockDim.x + threadIdx.x) >> 5;
    if (node >= N_NODES) return;
    int c = (blockIdx.y << 5) + (threadIdx.x & 31);
    int beg = g_rowptr[node], end = g_rowptr[node+1];
    float acc = 0.f;
    int e = beg;
    for (; e + 8 <= end; e += 8) {
        int s0 = __ldg(&g_col[e  ]), s1 = __ldg(&g_col[e+1]);
        int s2 = __ldg(&g_col[e+2]), s3 = __ldg(&g_col[e+3]);
        int s4 = __ldg(&g_col[e+4]), s5 = __ldg(&g_col[e+5]);
        int s6 = __ldg(&g_col[e+6]), s7 = __ldg(&g_col[e+7]);
        float v0 = __ldg(&g_val[e  ]), v1 = __ldg(&g_val[e+1]);
        float v2 = __ldg(&g_val[e+2]), v3 = __ldg(&g_val[e+3]);
        float v4 = __ldg(&g_val[e+4]), v5 = __ldg(&g_val[e+5]);
        float v6 = __ldg(&g_val[e+6]), v7 = __ldg(&g_val[e+7]);
        float x0 = __ldg(&in[s0*stride + c]);
        float x1 = __ldg(&in[s1*stride + c]);
        float x2 = __ldg(&in[s2*stride + c]);
        float x3 = __ldg(&in[s3*stride + c]);
        float x4 = __ldg(&in[s4*stride + c]);
        float x5 = __ldg(&in[s5*stride + c]);
        float x6 = __ldg(&in[s6*stride + c]);
        float x7 = __ldg(&in[s7*stride + c]);
        acc += v0*x0; acc += v1*x1; acc += v2*x2; acc += v3*x3;
        acc += v4*x4; acc += v5*x5; acc += v6*x6; acc += v7*x7;
    }
    if (e + 4 <= end) {
        int s0 = __ldg(&g_col[e  ]), s1 = __ldg(&g_col[e+1]);
        int s2 = __ldg(&g_col[e+2]), s3 = __ldg(&g_col[e+3]);
        float v0 = __ldg(&g_val[e  ]), v1 = __ldg(&g_val[e+1]);
        float v2 = __ldg(&g_val[e+2]), v3 = __ldg(&g_val[e+3]);
        float x0 = __ldg(&in[s0*stride + c]);
        float x1 = __ldg(&in[s1*stride + c]);
        float x2 = __ldg(&in[s2*stride + c]);
        float x3 = __ldg(&in[s3*stride + c]);
        acc += v0*x0; acc += v1*x1; acc += v2*x2; acc += v3*x3;
        e += 4;
    }
    if (e + 2 <= end) {
        int s0 = __ldg(&g_col[e]),   s1 = __ldg(&g_col[e+1]);
        float v0 = __ldg(&g_val[e]), v1 = __ldg(&g_val[e+1]);
        float x0 = __ldg(&in[s0*stride + c]);
        float x1 = __ldg(&in[s1*stride + c]);
        acc += v0*x0; acc += v1*x1;
        e += 2;
    }
    if (e < end) acc += __ldg(&g_val[e]) * __ldg(&in[__ldg(&g_col[e])*stride + c]);

    int idx = node*stride + c;
    float r = a * acc;
    if (sub) r -= sub[idx];
    out[idx] = r;
}

// ---------------- fused gate GEMM [N,200]x[200,128] + LSTM pointwise ----------------
__global__ void __launch_bounds__(512, 1) lstm_step_kernel(
    const float* __restrict__ w_c, const float* __restrict__ b_gates, int t)
{
    extern __shared__ float sm[];
    float* Wsm = sm;                     // 200*128 floats
    float* Asm = sm + KTOT*GATES;        // 128*201 floats
    int tid = threadIdx.x;
    int nodeBase = blockIdx.x * NODES_PER_BLK;

    for (int i = tid; i < KTOT*GATES; i += 512) Wsm[i] = g_Wcat[i];
    for (int i = tid; i < NODES_PER_BLK*KH; i += 512) {
        int nl = i / KH, kk = i - nl*KH;
        int node = nodeBase + nl;
        Asm[nl*ASTR + kk] = (node < N_NODES) ? g_Hcheb[(size_t)node*KH + kk] : 0.f;
    }
    for (int i = tid; i < NODES_PER_BLK*KX; i += 512) {
        int nl = i / KX, j = i - nl*KX;
        int k = j >> 3, f = j & 7;
        int node = nodeBase + nl;
        Asm[nl*ASTR + KH + j] = (node < N_NODES)
            ? g_XT[(size_t)k*((size_t)N_NODES*TF) + (size_t)node*TF + t*F_IN + f] : 0.f;
    }
    __syncthreads();

    int q  = tid >> 7;      // gate slice 0..3 (constant across a warp -> broadcast weight LDS)
    int nl = tid & 127;     // node within block
    unsigned long long acc[16];
#pragma unroll
    for (int j = 0; j < 16; ++j) acc[j] = 0ull;
    const float* arow = &Asm[nl*ASTR];
#pragma unroll 2
    for (int kk = 0; kk < KTOT; ++kk) {
        unsigned long long aa = bcast2(arow[kk]);
        const ulonglong2* w4 = (const ulonglong2*)&Wsm[kk*GATES + q*32];
#pragma unroll
        for (int j = 0; j < 8; ++j) {
            ulonglong2 w = w4[j];
            fma2(acc[2*j],   aa, w.x);
            fma2(acc[2*j+1], aa, w.y);
        }
    }
    __syncthreads();            // Asm free; reuse as gate buffer (stride 129)
    float* Gsm = Asm;
#pragma unroll
    for (int j = 0; j < 16; ++j) {
        unsigned int lo = (unsigned int)acc[j];
        unsigned int hi = (unsigned int)(acc[j] >> 32);
        Gsm[nl*129 + q*32 + 2*j]     = __uint_as_float(lo);
        Gsm[nl*129 + q*32 + 2*j + 1] = __uint_as_float(hi);
    }
    __syncthreads();

    for (int idx = tid; idx < NODES_PER_BLK*HID; idx += 512) {
        int nl2 = idx >> 5, h = idx & 31;
        int node = nodeBase + nl2;
        if (node >= N_NODES) continue;
        float Cold = g_C[(size_t)node*HID + h];
        const float* grow = &Gsm[nl2*129];
        float gi = grow[h]      + w_c[h]      * Cold + b_gates[h];
        float gf = grow[32 + h] + w_c[32 + h] * Cold + b_gates[32 + h];
        float gc = grow[64 + h]                      + b_gates[64 + h];
        float go = grow[96 + h]                      + b_gates[96 + h];
        float I  = sigmoidf_(gi);
        float F  = sigmoidf_(gf);
        float Tg = tanhf_(gc);
        float Cn = F * Cold + I * Tg;
        float O  = sigmoidf_(go + w_c[64 + h] * Cn);
        g_C[(size_t)node*HID + h] = Cn;
        g_Hcheb[(size_t)node*KH + h] = O * tanhf_(Cn);   // new H into cheb col 0
    }
}

// ---------------- final: out = relu(H) @ W_lin^T + b_lin ----------------
__global__ void final_out_kernel(const float* __restrict__ W_lin, const float* __restrict__ b_lin,
                                 float* __restrict__ out)
{
    int i = blockIdx.x*blockDim.x + threadIdx.x;
    if (i >= N_NODES*PERIODS) return;
    int n = i >> 3, p = i & 7;
    float s = b_lin[p];
    const float* hrow = &g_Hcheb[(size_t)n*KH];
    const float* wrow = &W_lin[p*HID];
#pragma unroll
    for (int h = 0; h < HID; ++h) s += fmaxf(hrow[h], 0.f) * wrow[h];
    out[i] = s;
}

// ---------------- launch ----------------
extern "C" void kernel_launch(void* const* d_in, const int* in_sizes, int n_in,
                              void* d_out, int out_size)
{
    const float* timesteps  = (const float*)d_in[0];
    const int*   edge_index = (const int*)  d_in[1];
    const float* Wx         = (const float*)d_in[2];
    const float* Wh         = (const float*)d_in[3];
    const float* w_c        = (const float*)d_in[4];
    const float* b_gates    = (const float*)d_in[5];
    const float* W_lin      = (const float*)d_in[6];
    const float* b_lin      = (const float*)d_in[7];
    float* out = (float*)d_out;

    cudaFuncSetAttribute(lstm_step_kernel,
                         cudaFuncAttributeMaxDynamicSharedMemorySize, SMEM_BYTES);

    void* p;
    cudaGetSymbolAddress(&p, g_XT);    float* XT    = (float*)p;
    cudaGetSymbolAddress(&p, g_Hcheb); float* Hcheb = (float*)p;

    // setup: 5 launches so ncu -s 5 profiles the first cheb gather
    init_kernel          <<<(N_NODES*KH + 255)/256, 256>>>(timesteps, Wx, Wh);
    edge_deg_count_kernel<<<(N_EDGES + 255)/256, 256>>>(edge_index);
    compute_dis_kernel   <<<(N_NODES + 255)/256, 256>>>();
    scan_kernel          <<<1, 1024>>>();
    scatter_edges_kernel <<<(N_EDGES + 255)/256, 256>>>(edge_index);

    const size_t plane = (size_t)N_NODES*TF;
    dim3 chebGrid2((N_NODES + 7)/8, 2);   // C=64 (all timesteps batched)
    dim3 chebGrid1((N_NODES + 7)/8, 1);   // C=32

    // Chebyshev planes of the inputs: T1..T4 over [N, 64]
    for (int k = 1; k < KCHEB; ++k) {
        cheb_step_kernel<<<chebGrid2, 256>>>(
            XT + (size_t)(k-1)*plane,
            (k >= 2) ? XT + (size_t)(k-2)*plane : nullptr,
            XT + (size_t)k*plane,
            TF, (k == 1) ? 1.f : 2.f);
    }

    const int nblk = (N_NODES + NODES_PER_BLK - 1)/NODES_PER_BLK;
    for (int t = 0; t < T_STEPS; ++t) {
        if (t > 0) {  // t==0: H=0 -> all hidden cheb planes stay 0 (zeroed in init)
            for (int k = 1; k < KCHEB; ++k) {
                cheb_step_kernel<<<chebGrid1, 256>>>(
                    Hcheb + 32*(k-1),
                    (k >= 2) ? Hcheb + 32*(k-2) : nullptr,
                    Hcheb + 32*k,
                    KH, (k == 1) ? 1.f : 2.f);
            }
        }
        lstm_step_kernel<<<nblk, 512, SMEM_BYTES>>>(w_c, b_gates, t);
    }

    final_out_kernel<<<(N_NODES*PERIODS + 255)/256, 256>>>(W_lin, b_lin, out);
}

// round 8
// speedup vs baseline: 1.1195x; 1.0619x over previous
#include <cuda_runtime.h>
#include <cstdint>

// ---------------- problem constants ----------------
#define N_NODES 30000
#define N_EDGES 480000
#define T_STEPS 8
#define F_IN    8
#define HID     32
#define KCHEB   5
#define PERIODS 8

#define KH   (KCHEB*HID)    // 160 hidden-cheb columns
#define KX   (KCHEB*F_IN)   // 40 input-cheb columns
#define KTOT (KH+KX)        // 200
#define GATES 128           // 4*HID
#define TF   (T_STEPS*F_IN) // 64

#define NODES_PER_BLK 128
#define ASTR (KTOT+1)       // 201, conflict-free smem stride
#define SMEM_BYTES ((KTOT*GATES + NODES_PER_BLK*ASTR)*4)

// ---------------- device scratch (static, allocation-free) ----------------
__device__ int   g_deg[N_NODES];
__device__ int   g_counts[N_NODES];
__device__ int   g_cursor[N_NODES];
__device__ float g_dis[N_NODES];
__device__ int   g_rowptr[N_NODES+1];
__device__ int   g_col[N_EDGES];
__device__ float g_val[N_EDGES];
__device__ float g_XT[(size_t)KCHEB*N_NODES*TF];   // cheb planes of inputs, [k][n][t*8+f]
__device__ float g_Hcheb[(size_t)N_NODES*KH];      // [n][k*32+h]; cols 0:32 hold H
__device__ float g_C[(size_t)N_NODES*HID];
__device__ float g_Wcat[KTOT*GATES];               // flattened [200][128] gate weights

// ---------------- helpers ----------------
__device__ __forceinline__ float sigmoidf_(float x){ return 1.f/(1.f+__expf(-x)); }
__device__ __forceinline__ float tanhf_(float x){ return 2.f/(1.f+__expf(-2.f*x)) - 1.f; }

__device__ __forceinline__ unsigned long long bcast2(float a){
    unsigned long long r;
    asm("mov.b64 %0, {%1, %1};" : "=l"(r) : "r"(__float_as_uint(a)));
    return r;
}
__device__ __forceinline__ void fma2(unsigned long long &d, unsigned long long a, unsigned long long b){
    asm("fma.rn.f32x2 %0, %1, %2, %0;" : "+l"(d) : "l"(a), "l"(b));
}

// ---------------- fused setup: zero + weight flatten + input transpose ----------------
__global__ void init_kernel(const float* __restrict__ ts,
                            const float* __restrict__ Wx, const float* __restrict__ Wh){
    int i = blockIdx.x*blockDim.x + threadIdx.x;
    if (i < N_NODES) { g_deg[i] = 0; g_counts[i] = 0; g_cursor[i] = 0; }
    if (i < N_NODES*HID) g_C[i] = 0.f;
    if (i < N_NODES*KH) g_Hcheb[i] = 0.f;   // all 5 cheb planes of H zeroed (H0 = 0)
    if (i < KTOT*GATES) {
        int row = i / GATES, colc = i - row*GATES;
        int g = colc >> 5, h = colc & 31;
        float v;
        if (row < KH) {
            int k = row >> 5, ii = row & 31;
            v = Wh[((g*KCHEB + k)*HID + ii)*HID + h];
        } else {
            int r = row - KH;
            int k = r >> 3, f = r & 7;
            v = Wx[((g*KCHEB + k)*F_IN + f)*HID + h];
        }
        g_Wcat[i] = v;
    }
    if (i < N_NODES*TF) {
        int n = i / TF, r = i - n*TF;
        int t = r >> 3, f = r & 7;
        g_XT[i] = ts[((size_t)t*N_NODES + n)*F_IN + f];
    }
}

__global__ void edge_deg_count_kernel(const int* __restrict__ ei){
    int e = blockIdx.x*blockDim.x + threadIdx.x;
    if (e >= N_EDGES) return;
    int s = ei[e], d = ei[N_EDGES + e];
    if (s != d) atomicAdd(&g_deg[s], 1);
    atomicAdd(&g_counts[d], 1);
}

__global__ void compute_dis_kernel(){
    int i = blockIdx.x*blockDim.x + threadIdx.x;
    if (i >= N_NODES) return;
    int d = g_deg[i];
    g_dis[i] = (d > 0) ? rsqrtf((float)d) : 0.f;
}

// shuffle-based single-block scan: 4 barriers per 1024-tile instead of 20
__global__ void scan_kernel(){
    __shared__ int wsum[32];
    __shared__ int s_carry;
    int t = threadIdx.x, lane = t & 31, wid = t >> 5;
    if (t == 0) s_carry = 0;
    __syncthreads();
    for (int base = 0; base < N_NODES; base += 1024) {
        int i = base + t;
        int v = (i < N_NODES) ? g_counts[i] : 0;
        int x = v;
#pragma unroll
        for (int off = 1; off < 32; off <<= 1) {
            int y = __shfl_up_sync(0xffffffffu, x, off);
            if (lane >= off) x += y;
        }
        if (lane == 31) wsum[wid] = x;
        __syncthreads();
        if (wid == 0) {
            int s = wsum[lane];
#pragma unroll
            for (int off = 1; off < 32; off <<= 1) {
                int y = __shfl_up_sync(0xffffffffu, s, off);
                if (lane >= off) s += y;
            }
            wsum[lane] = s;
        }
        __syncthreads();
        int pre   = (wid > 0) ? wsum[wid-1] : 0;
        int carry = s_carry;
        if (i < N_NODES) g_rowptr[i] = carry + pre + x - v;   // exclusive
        __syncthreads();
        if (t == 0) s_carry = carry + wsum[31];
        __syncthreads();
    }
    if (t == 0) g_rowptr[N_NODES] = s_carry;
}

__global__ void scatter_edges_kernel(const int* __restrict__ ei){
    int e = blockIdx.x*blockDim.x + threadIdx.x;
    if (e >= N_EDGES) return;
    int s = ei[e], d = ei[N_EDGES + e];
    int pos = g_rowptr[d] + atomicAdd(&g_cursor[d], 1);
    g_col[pos] = s;
    g_val[pos] = (s == d) ? 0.f : -g_dis[s]*g_dis[d];  // minus of lap folded in
}

// ---------------- Chebyshev step: out = a * Lhat(in) - sub ----------------
// warp per node, lane per channel; grid.y selects 32-channel segment.
// Manually unrolled x8 to maximize gather MLP (L2-latency hiding).
__global__ void __launch_bounds__(256) cheb_step_kernel(
    const float* __restrict__ in, const float* __restrict__ sub,
    float* __restrict__ out, int stride, float a)
{
    int node = (blockIdx.x * blockDim.x + threadIdx.x) >> 5;
    if (node >= N_NODES) return;
    int c = (blockIdx.y << 5) + (threadIdx.x & 31);
    int beg = g_rowptr[node], end = g_rowptr[node+1];
    float acc = 0.f;
    int e = beg;
    for (; e + 8 <= end; e += 8) {
        int s0 = __ldg(&g_col[e  ]), s1 = __ldg(&g_col[e+1]);
        int s2 = __ldg(&g_col[e+2]), s3 = __ldg(&g_col[e+3]);
        int s4 = __ldg(&g_col[e+4]), s5 = __ldg(&g_col[e+5]);
        int s6 = __ldg(&g_col[e+6]), s7 = __ldg(&g_col[e+7]);
        float v0 = __ldg(&g_val[e  ]), v1 = __ldg(&g_val[e+1]);
        float v2 = __ldg(&g_val[e+2]), v3 = __ldg(&g_val[e+3]);
        float v4 = __ldg(&g_val[e+4]), v5 = __ldg(&g_val[e+5]);
        float v6 = __ldg(&g_val[e+6]), v7 = __ldg(&g_val[e+7]);
        float x0 = __ldg(&in[s0*stride + c]);
        float x1 = __ldg(&in[s1*stride + c]);
        float x2 = __ldg(&in[s2*stride + c]);
        float x3 = __ldg(&in[s3*stride + c]);
        float x4 = __ldg(&in[s4*stride + c]);
        float x5 = __ldg(&in[s5*stride + c]);
        float x6 = __ldg(&in[s6*stride + c]);
        float x7 = __ldg(&in[s7*stride + c]);
        acc += v0*x0; acc += v1*x1; acc += v2*x2; acc += v3*x3;
        acc += v4*x4; acc += v5*x5; acc += v6*x6; acc += v7*x7;
    }
    if (e + 4 <= end) {
        int s0 = __ldg(&g_col[e  ]), s1 = __ldg(&g_col[e+1]);
        int s2 = __ldg(&g_col[e+2]), s3 = __ldg(&g_col[e+3]);
        float v0 = __ldg(&g_val[e  ]), v1 = __ldg(&g_val[e+1]);
        float v2 = __ldg(&g_val[e+2]), v3 = __ldg(&g_val[e+3]);
        float x0 = __ldg(&in[s0*stride + c]);
        float x1 = __ldg(&in[s1*stride + c]);
        float x2 = __ldg(&in[s2*stride + c]);
        float x3 = __ldg(&in[s3*stride + c]);
        acc += v0*x0; acc += v1*x1; acc += v2*x2; acc += v3*x3;
        e += 4;
    }
    if (e + 2 <= end) {
        int s0 = __ldg(&g_col[e]),   s1 = __ldg(&g_col[e+1]);
        float v0 = __ldg(&g_val[e]), v1 = __ldg(&g_val[e+1]);
        float x0 = __ldg(&in[s0*stride + c]);
        float x1 = __ldg(&in[s1*stride + c]);
        acc += v0*x0; acc += v1*x1;
        e += 2;
    }
    if (e < end) acc += __ldg(&g_val[e]) * __ldg(&in[__ldg(&g_col[e])*stride + c]);

    int idx = node*stride + c;
    float r = a * acc;
    if (sub) r -= sub[idx];
    out[idx] = r;
}

// ---------------- fused gate GEMM [N,200]x[200,128] + LSTM pointwise ----------------
// 256 threads, each computes 2 nodes x 32 outputs (one gate slice):
// each broadcast weight LDS.128 now feeds 4 FFMA2 -> smem crossbar halved.
// kbeg: first K column (t==0 -> KH, hidden cheb planes are all zero).
__global__ void __launch_bounds__(256, 1) lstm_step_kernel(
    const float* __restrict__ w_c, const float* __restrict__ b_gates, int t, int kbeg)
{
    extern __shared__ float sm[];
    float* Wsm = sm;                     // 200*128 floats
    float* Asm = sm + KTOT*GATES;        // 128*201 floats
    int tid = threadIdx.x;
    int nodeBase = blockIdx.x * NODES_PER_BLK;

    for (int i = kbeg*GATES + tid; i < KTOT*GATES; i += 256) Wsm[i] = g_Wcat[i];
    if (kbeg == 0) {
        for (int i = tid; i < NODES_PER_BLK*KH; i += 256) {
            int nl = i / KH, kk = i - nl*KH;
            int node = nodeBase + nl;
            Asm[nl*ASTR + kk] = (node < N_NODES) ? g_Hcheb[(size_t)node*KH + kk] : 0.f;
        }
    }
    for (int i = tid; i < NODES_PER_BLK*KX; i += 256) {
        int nl = i / KX, j = i - nl*KX;
        int k = j >> 3, f = j & 7;
        int node = nodeBase + nl;
        Asm[nl*ASTR + KH + j] = (node < N_NODES)
            ? g_XT[(size_t)k*((size_t)N_NODES*TF) + (size_t)node*TF + t*F_IN + f] : 0.f;
    }
    __syncthreads();

    int q = tid >> 6;        // gate slice 0..3 (constant across a warp -> broadcast weight LDS)
    int r = tid & 63;        // node pair selector: nodes r and r+64
    unsigned long long acc0[16], acc1[16];
#pragma unroll
    for (int j = 0; j < 16; ++j) { acc0[j] = 0ull; acc1[j] = 0ull; }
    const float* arow0 = &Asm[r*ASTR];
    const float* arow1 = &Asm[(r+64)*ASTR];
#pragma unroll 2
    for (int kk = kbeg; kk < KTOT; ++kk) {
        unsigned long long aa0 = bcast2(arow0[kk]);
        unsigned long long aa1 = bcast2(arow1[kk]);
        const ulonglong2* w4 = (const ulonglong2*)&Wsm[kk*GATES + q*32];
#pragma unroll
        for (int j = 0; j < 8; ++j) {
            ulonglong2 w = w4[j];
            fma2(acc0[2*j],   aa0, w.x);
            fma2(acc0[2*j+1], aa0, w.y);
            fma2(acc1[2*j],   aa1, w.x);
            fma2(acc1[2*j+1], aa1, w.y);
        }
    }
    __syncthreads();            // Asm free; reuse as gate buffer (stride 129)
    float* Gsm = Asm;
#pragma unroll
    for (int j = 0; j < 16; ++j) {
        Gsm[r*129      + q*32 + 2*j]     = __uint_as_float((unsigned int)acc0[j]);
        Gsm[r*129      + q*32 + 2*j + 1] = __uint_as_float((unsigned int)(acc0[j] >> 32));
        Gsm[(r+64)*129 + q*32 + 2*j]     = __uint_as_float((unsigned int)acc1[j]);
        Gsm[(r+64)*129 + q*32 + 2*j + 1] = __uint_as_float((unsigned int)(acc1[j] >> 32));
    }
    __syncthreads();

    for (int idx = tid; idx < NODES_PER_BLK*HID; idx += 256) {
        int nl2 = idx >> 5, h = idx & 31;
        int node = nodeBase + nl2;
        if (node >= N_NODES) continue;
        float Cold = g_C[(size_t)node*HID + h];
        const float* grow = &Gsm[nl2*129];
        float gi = grow[h]      + w_c[h]      * Cold + b_gates[h];
        float gf = grow[32 + h] + w_c[32 + h] * Cold + b_gates[32 + h];
        float gc = grow[64 + h]                      + b_gates[64 + h];
        float go = grow[96 + h]                      + b_gates[96 + h];
        float I  = sigmoidf_(gi);
        float F  = sigmoidf_(gf);
        float Tg = tanhf_(gc);
        float Cn = F * Cold + I * Tg;
        float O  = sigmoidf_(go + w_c[64 + h] * Cn);
        g_C[(size_t)node*HID + h] = Cn;
        g_Hcheb[(size_t)node*KH + h] = O * tanhf_(Cn);   // new H into cheb col 0
    }
}

// ---------------- final: out = relu(H) @ W_lin^T + b_lin ----------------
__global__ void final_out_kernel(const float* __restrict__ W_lin, const float* __restrict__ b_lin,
                                 float* __restrict__ out)
{
    int i = blockIdx.x*blockDim.x + threadIdx.x;
    if (i >= N_NODES*PERIODS) return;
    int n = i >> 3, p = i & 7;
    float s = b_lin[p];
    const float* hrow = &g_Hcheb[(size_t)n*KH];
    const float* wrow = &W_lin[p*HID];
#pragma unroll
    for (int h = 0; h < HID; ++h) s += fmaxf(hrow[h], 0.f) * wrow[h];
    out[i] = s;
}

// ---------------- launch ----------------
extern "C" void kernel_launch(void* const* d_in, const int* in_sizes, int n_in,
                              void* d_out, int out_size)
{
    const float* timesteps  = (const float*)d_in[0];
    const int*   edge_index = (const int*)  d_in[1];
    const float* Wx         = (const float*)d_in[2];
    const float* Wh         = (const float*)d_in[3];
    const float* w_c        = (const float*)d_in[4];
    const float* b_gates    = (const float*)d_in[5];
    const float* W_lin      = (const float*)d_in[6];
    const float* b_lin      = (const float*)d_in[7];
    float* out = (float*)d_out;

    cudaFuncSetAttribute(lstm_step_kernel,
                         cudaFuncAttributeMaxDynamicSharedMemorySize, SMEM_BYTES);

    void* p;
    cudaGetSymbolAddress(&p, g_XT);    float* XT    = (float*)p;
    cudaGetSymbolAddress(&p, g_Hcheb); float* Hcheb = (float*)p;

    init_kernel          <<<(N_NODES*KH + 255)/256, 256>>>(timesteps, Wx, Wh);
    edge_deg_count_kernel<<<(N_EDGES + 255)/256, 256>>>(edge_index);
    compute_dis_kernel   <<<(N_NODES + 255)/256, 256>>>();
    scan_kernel          <<<1, 1024>>>();
    scatter_edges_kernel <<<(N_EDGES + 255)/256, 256>>>(edge_index);

    const size_t plane = (size_t)N_NODES*TF;
    dim3 chebGrid2((N_NODES + 7)/8, 2);   // C=64 (all timesteps batched)
    dim3 chebGrid1((N_NODES + 7)/8, 1);   // C=32

    // Chebyshev planes of the inputs: T1..T4 over [N, 64]
    for (int k = 1; k < KCHEB; ++k) {
        cheb_step_kernel<<<chebGrid2, 256>>>(
            XT + (size_t)(k-1)*plane,
            (k >= 2) ? XT + (size_t)(k-2)*plane : nullptr,
            XT + (size_t)k*plane,
            TF, (k == 1) ? 1.f : 2.f);
    }

    const int nblk = (N_NODES + NODES_PER_BLK - 1)/NODES_PER_BLK;
    for (int t = 0; t < T_STEPS; ++t) {
        if (t > 0) {  // t==0: H=0 -> all hidden cheb planes stay 0 (zeroed in init)
            for (int k = 1; k < KCHEB; ++k) {
                cheb_step_kernel<<<chebGrid1, 256>>>(
                    Hcheb + 32*(k-1),
                    (k >= 2) ? Hcheb + 32*(k-2) : nullptr,
                    Hcheb + 32*k,
                    KH, (k == 1) ? 1.f : 2.f);
            }
        }
        lstm_step_kernel<<<nblk, 256, SMEM_BYTES>>>(w_c, b_gates, t, (t == 0) ? KH : 0);
    }

    final_out_kernel<<<(N_NODES*PERIODS + 255)/256, 256>>>(W_lin, b_lin, out);
}

// round 13
// speedup vs baseline: 1.2005x; 1.0723x over previous
#include <cuda_runtime.h>
#include <cstdint>

// ---------------- problem constants ----------------
#define N_NODES 30000
#define N_EDGES 480000
#define T_STEPS 8
#define F_IN    8
#define HID     32
#define KCHEB   5
#define PERIODS 8

#define KH   (KCHEB*HID)    // 160 hidden-cheb columns
#define KX   (KCHEB*F_IN)   // 40 input-cheb columns
#define KTOT (KH+KX)        // 200
#define GATES 128           // 4*HID
#define TF   (T_STEPS*F_IN) // 64

#define NODES_PER_BLK 128
#define AT_STR 132          // transposed A stride in floats (128 nodes + pad, %4==0 for LDS.128)
#define GSTR   130          // gate buffer stride (even -> 8B-aligned ull stores)
#define SMEM_BYTES ((KTOT*GATES + KTOT*AT_STR)*4)   // 208000 B

#define SCAN_BLK 30         // ceil(30000/1024)

// ---------------- device scratch (static, allocation-free) ----------------
__device__ int   g_deg[N_NODES];
__device__ int   g_counts[N_NODES];
__device__ int   g_cursor[N_NODES];
__device__ float g_dis[N_NODES];
__device__ int   g_rowptr[N_NODES+1];
__device__ int   g_partials[SCAN_BLK];
__device__ int   g_col[N_EDGES];
__device__ float g_val[N_EDGES];
__device__ float g_XT[(size_t)KCHEB*N_NODES*TF];   // cheb planes of inputs, [k][n][t*8+f]
__device__ float g_Hcheb[(size_t)N_NODES*KH];      // [n][k*32+h]; cols 0:32 hold H
__device__ float g_C[(size_t)N_NODES*HID];
__device__ float g_Wcat[KTOT*GATES];               // flattened [200][128] gate weights

// ---------------- helpers ----------------
__device__ __forceinline__ float sigmoidf_(float x){ return 1.f/(1.f+__expf(-x)); }
__device__ __forceinline__ float tanhf_(float x){ return 2.f/(1.f+__expf(-2.f*x)) - 1.f; }

__device__ __forceinline__ unsigned long long bcast2(float a){
    unsigned long long r;
    asm("mov.b64 %0, {%1, %1};" : "=l"(r) : "r"(__float_as_uint(a)));
    return r;
}
__device__ __forceinline__ void fma2(unsigned long long &d, unsigned long long a, unsigned long long b){
    asm("fma.rn.f32x2 %0, %1, %2, %0;" : "+l"(d) : "l"(a), "l"(b));
}

// ---------------- fused setup: zero + weight flatten + input transpose ----------------
__global__ void init_kernel(const float* __restrict__ ts,
                            const float* __restrict__ Wx, const float* __restrict__ Wh){
    int i = blockIdx.x*blockDim.x + threadIdx.x;
    if (i < N_NODES) { g_deg[i] = 0; g_counts[i] = 0; g_cursor[i] = 0; }
    if (i < N_NODES*HID) g_C[i] = 0.f;
    if (i < N_NODES*KH) g_Hcheb[i] = 0.f;   // all 5 cheb planes of H zeroed (H0 = 0)
    if (i < KTOT*GATES) {
        int row = i / GATES, colc = i - row*GATES;
        int g = colc >> 5, h = colc & 31;
        float v;
        if (row < KH) {
            int k = row >> 5, ii = row & 31;
            v = Wh[((g*KCHEB + k)*HID + ii)*HID + h];
        } else {
            int r = row - KH;
            int k = r >> 3, f = r & 7;
            v = Wx[((g*KCHEB + k)*F_IN + f)*HID + h];
        }
        g_Wcat[i] = v;
    }
    if (i < N_NODES*TF) {
        int n = i / TF, r = i - n*TF;
        int t = r >> 3, f = r & 7;
        g_XT[i] = ts[((size_t)t*N_NODES + n)*F_IN + f];
    }
}

__global__ void edge_deg_count_kernel(const int* __restrict__ ei){
    int e = blockIdx.x*blockDim.x + threadIdx.x;
    if (e >= N_EDGES) return;
    int s = ei[e], d = ei[N_EDGES + e];
    if (s != d) atomicAdd(&g_deg[s], 1);
    atomicAdd(&g_counts[d], 1);
}

// multi-block scan phase 1: per-block exclusive scan + block total; also computes dis
__global__ void scan_part_kernel(){
    __shared__ int wsum[32];
    int b = blockIdx.x, t = threadIdx.x;
    int lane = t & 31, wid = t >> 5;
    int i = b*1024 + t;
    if (i < N_NODES) {
        int d = g_deg[i];
        g_dis[i] = (d > 0) ? rsqrtf((float)d) : 0.f;
    }
    int v = (i < N_NODES) ? g_counts[i] : 0;
    int x = v;
#pragma unroll
    for (int off = 1; off < 32; off <<= 1) {
        int y = __shfl_up_sync(0xffffffffu, x, off);
        if (lane >= off) x += y;
    }
    if (lane == 31) wsum[wid] = x;
    __syncthreads();
    if (wid == 0) {
        int s = wsum[lane];
#pragma unroll
        for (int off = 1; off < 32; off <<= 1) {
            int y = __shfl_up_sync(0xffffffffu, s, off);
            if (lane >= off) s += y;
        }
        wsum[lane] = s;
    }
    __syncthreads();
    int pre = (wid > 0) ? wsum[wid-1] : 0;
    if (i < N_NODES) g_rowptr[i] = pre + x - v;      // block-local exclusive
    if (t == 1023) g_partials[b] = pre + x;          // block total (inclusive)
}

// phase 2: add cross-block offsets
__global__ void scan_fix_kernel(){
    __shared__ int s_off;
    int b = blockIdx.x, t = threadIdx.x;
    if (t == 0) {
        int s = 0;
        for (int j = 0; j < b; ++j) s += g_partials[j];
        s_off = s;
    }
    __syncthreads();
    int i = b*1024 + t;
    if (i < N_NODES) g_rowptr[i] += s_off;
    if (b == SCAN_BLK-1 && t == 0) g_rowptr[N_NODES] = s_off + g_partials[b];
}

__global__ void scatter_edges_kernel(const int* __restrict__ ei){
    int e = blockIdx.x*blockDim.x + threadIdx.x;
    if (e >= N_EDGES) return;
    int s = ei[e], d = ei[N_EDGES + e];
    int pos = g_rowptr[d] + atomicAdd(&g_cursor[d], 1);
    g_col[pos] = s;
    g_val[pos] = (s == d) ? 0.f : -g_dis[s]*g_dis[d];  // minus of lap folded in
}

// ---------------- Chebyshev step: out = a * Lhat(in) - sub ----------------
// warp per node, lane per channel; grid.y selects 32-channel segment.
// Manually unrolled x8 to maximize gather MLP (L2-latency hiding).
__global__ void __launch_bounds__(256) cheb_step_kernel(
    const float* __restrict__ in, const float* __restrict__ sub,
    float* __restrict__ out, int stride, float a)
{
    int node = (blockIdx.x * blockDim.x + threadIdx.x) >> 5;
    if (node >= N_NODES) return;
    int c = (blockIdx.y << 5) + (threadIdx.x & 31);
    int beg = g_rowptr[node], end = g_rowptr[node+1];
    float acc = 0.f;
    int e = beg;
    for (; e + 8 <= end; e += 8) {
        int s0 = __ldg(&g_col[e  ]), s1 = __ldg(&g_col[e+1]);
        int s2 = __ldg(&g_col[e+2]), s3 = __ldg(&g_col[e+3]);
        int s4 = __ldg(&g_col[e+4]), s5 = __ldg(&g_col[e+5]);
        int s6 = __ldg(&g_col[e+6]), s7 = __ldg(&g_col[e+7]);
        float v0 = __ldg(&g_val[e  ]), v1 = __ldg(&g_val[e+1]);
        float v2 = __ldg(&g_val[e+2]), v3 = __ldg(&g_val[e+3]);
        float v4 = __ldg(&g_val[e+4]), v5 = __ldg(&g_val[e+5]);
        float v6 = __ldg(&g_val[e+6]), v7 = __ldg(&g_val[e+7]);
        float x0 = __ldg(&in[s0*stride + c]);
        float x1 = __ldg(&in[s1*stride + c]);
        float x2 = __ldg(&in[s2*stride + c]);
        float x3 = __ldg(&in[s3*stride + c]);
        float x4 = __ldg(&in[s4*stride + c]);
        float x5 = __ldg(&in[s5*stride + c]);
        float x6 = __ldg(&in[s6*stride + c]);
        float x7 = __ldg(&in[s7*stride + c]);
        acc += v0*x0; acc += v1*x1; acc += v2*x2; acc += v3*x3;
        acc += v4*x4; acc += v5*x5; acc += v6*x6; acc += v7*x7;
    }
    if (e + 4 <= end) {
        int s0 = __ldg(&g_col[e  ]), s1 = __ldg(&g_col[e+1]);
        int s2 = __ldg(&g_col[e+2]), s3 = __ldg(&g_col[e+3]);
        float v0 = __ldg(&g_val[e  ]), v1 = __ldg(&g_val[e+1]);
        float v2 = __ldg(&g_val[e+2]), v3 = __ldg(&g_val[e+3]);
        float x0 = __ldg(&in[s0*stride + c]);
        float x1 = __ldg(&in[s1*stride + c]);
        float x2 = __ldg(&in[s2*stride + c]);
        float x3 = __ldg(&in[s3*stride + c]);
        acc += v0*x0; acc += v1*x1; acc += v2*x2; acc += v3*x3;
        e += 4;
    }
    if (e + 2 <= end) {
        int s0 = __ldg(&g_col[e]),   s1 = __ldg(&g_col[e+1]);
        float v0 = __ldg(&g_val[e]), v1 = __ldg(&g_val[e+1]);
        float x0 = __ldg(&in[s0*stride + c]);
        float x1 = __ldg(&in[s1*stride + c]);
        acc += v0*x0; acc += v1*x1;
        e += 2;
    }
    if (e < end) acc += __ldg(&g_val[e]) * __ldg(&in[__ldg(&g_col[e])*stride + c]);

    int idx = node*stride + c;
    float r = a * acc;
    if (sub) r -= sub[idx];
    out[idx] = r;
}

// ---------------- fused gate GEMM [128,200]x[200,128] + LSTM pointwise ----------------
// Outer-product register tiling: 256 threads = 16 node-groups x 16 gate-groups,
// each thread computes an 8x8 tile (as 8x4 f32x2 accumulators).
// A is staged TRANSPOSED in smem: At[kk][node] so node-direction loads are LDS.128.
// kbeg: first K column (t==0 -> KH, hidden cheb planes are all zero).
__global__ void __launch_bounds__(256, 1) lstm_step_kernel(
    const float* __restrict__ w_c, const float* __restrict__ b_gates, int t, int kbeg)
{
    extern __shared__ float sm[];
    float* Wsm = sm;                     // [KTOT][128]
    float* At  = sm + KTOT*GATES;        // [KTOT][AT_STR]
    int tid = threadIdx.x;
    int nodeBase = blockIdx.x * NODES_PER_BLK;

    // stage weights (rows kbeg..KTOT)
    for (int i = kbeg*GATES + tid; i < KTOT*GATES; i += 256) Wsm[i] = g_Wcat[i];

    // stage hidden cheb part of At (transposed), float4 reads + conflict-light STS.32
    if (kbeg == 0) {
        int nl = tid >> 1, half = tid & 1;
        int node = nodeBase + nl;
        bool ok = node < N_NODES;
        const float4* src = (const float4*)&g_Hcheb[(size_t)node*KH + half*(KH/2)];
#pragma unroll
        for (int q4 = 0; q4 < KH/8; ++q4) {      // 20 float4 per half-row
            float4 v = ok ? __ldg(&src[q4]) : make_float4(0.f,0.f,0.f,0.f);
            int kk = half*(KH/2) + q4*4;
            At[(kk+0)*AT_STR + nl] = v.x;
            At[(kk+1)*AT_STR + nl] = v.y;
            At[(kk+2)*AT_STR + nl] = v.z;
            At[(kk+3)*AT_STR + nl] = v.w;
        }
    }
    // stage input cheb part of At (transposed): 10 float4 per node
    {
        const size_t plane = (size_t)N_NODES*TF;
        for (int i = tid; i < NODES_PER_BLK*10; i += 256) {
            int nl = i / 10, j4 = i - nl*10;
            int k = j4 >> 1, f4 = (j4 & 1)*4;
            int node = nodeBase + nl;
            float4 v = (node < N_NODES)
                ? __ldg((const float4*)&g_XT[(size_t)k*plane + (size_t)node*TF + t*F_IN + f4])
                : make_float4(0.f,0.f,0.f,0.f);
            int kk = KH + k*F_IN + f4;
            At[(kk+0)*AT_STR + nl] = v.x;
            At[(kk+1)*AT_STR + nl] = v.y;
            At[(kk+2)*AT_STR + nl] = v.z;
            At[(kk+3)*AT_STR + nl] = v.w;
        }
    }
    __syncthreads();

    int jg = tid & 15;      // gate group: gates 8*jg .. 8*jg+7
    int ig = tid >> 4;      // node group: nodes 8*ig .. 8*ig+7
    unsigned long long acc[8][4];
#pragma unroll
    for (int m = 0; m < 8; ++m)
#pragma unroll
        for (int c = 0; c < 4; ++c) acc[m][c] = 0ull;

    const float* abase = &At[ig*8];
    const float* wbase = &Wsm[jg*8];
#pragma unroll 2
    for (int kk = kbeg; kk < KTOT; ++kk) {
        float4 a0 = *(const float4*)&abase[kk*AT_STR];
        float4 a1 = *(const float4*)&abase[kk*AT_STR + 4];
        ulonglong2 w0 = *(const ulonglong2*)&wbase[kk*GATES];
        ulonglong2 w1 = *(const ulonglong2*)&wbase[kk*GATES + 4];
        unsigned long long A0 = bcast2(a0.x), A1 = bcast2(a0.y);
        unsigned long long A2 = bcast2(a0.z), A3 = bcast2(a0.w);
        unsigned long long A4 = bcast2(a1.x), A5 = bcast2(a1.y);
        unsigned long long A6 = bcast2(a1.z), A7 = bcast2(a1.w);
        fma2(acc[0][0],A0,w0.x); fma2(acc[0][1],A0,w0.y); fma2(acc[0][2],A0,w1.x); fma2(acc[0][3],A0,w1.y);
        fma2(acc[1][0],A1,w0.x); fma2(acc[1][1],A1,w0.y); fma2(acc[1][2],A1,w1.x); fma2(acc[1][3],A1,w1.y);
        fma2(acc[2][0],A2,w0.x); fma2(acc[2][1],A2,w0.y); fma2(acc[2][2],A2,w1.x); fma2(acc[2][3],A2,w1.y);
        fma2(acc[3][0],A3,w0.x); fma2(acc[3][1],A3,w0.y); fma2(acc[3][2],A3,w1.x); fma2(acc[3][3],A3,w1.y);
        fma2(acc[4][0],A4,w0.x); fma2(acc[4][1],A4,w0.y); fma2(acc[4][2],A4,w1.x); fma2(acc[4][3],A4,w1.y);
        fma2(acc[5][0],A5,w0.x); fma2(acc[5][1],A5,w0.y); fma2(acc[5][2],A5,w1.x); fma2(acc[5][3],A5,w1.y);
        fma2(acc[6][0],A6,w0.x); fma2(acc[6][1],A6,w0.y); fma2(acc[6][2],A6,w1.x); fma2(acc[6][3],A6,w1.y);
        fma2(acc[7][0],A7,w0.x); fma2(acc[7][1],A7,w0.y); fma2(acc[7][2],A7,w1.x); fma2(acc[7][3],A7,w1.y);
    }
    __syncthreads();            // At free; reuse as gate buffer (stride GSTR)
    float* Gsm = At;
#pragma unroll
    for (int m = 0; m < 8; ++m) {
        int row = (ig*8 + m)*GSTR + jg*8;
#pragma unroll
        for (int c = 0; c < 4; ++c)
            *(unsigned long long*)&Gsm[row + 2*c] = acc[m][c];
    }
    __syncthreads();

    for (int idx = tid; idx < NODES_PER_BLK*HID; idx += 256) {
        int nl2 = idx >> 5, h = idx & 31;
        int node = nodeBase + nl2;
        if (node >= N_NODES) continue;
        float Cold = g_C[(size_t)node*HID + h];
        const float* grow = &Gsm[nl2*GSTR];
        float gi = grow[h]      + w_c[h]      * Cold + b_gates[h];
        float gf = grow[32 + h] + w_c[32 + h] * Cold + b_gates[32 + h];
        float gc = grow[64 + h]                      + b_gates[64 + h];
        float go = grow[96 + h]                      + b_gates[96 + h];
        float I  = sigmoidf_(gi);
        float F  = sigmoidf_(gf);
        float Tg = tanhf_(gc);
        float Cn = F * Cold + I * Tg;
        float O  = sigmoidf_(go + w_c[64 + h] * Cn);
        g_C[(size_t)node*HID + h] = Cn;
        g_Hcheb[(size_t)node*KH + h] = O * tanhf_(Cn);   // new H into cheb col 0
    }
}

// ---------------- final: out = relu(H) @ W_lin^T + b_lin ----------------
__global__ void final_out_kernel(const float* __restrict__ W_lin, const float* __restrict__ b_lin,
                                 float* __restrict__ out)
{
    int i = blockIdx.x*blockDim.x + threadIdx.x;
    if (i >= N_NODES*PERIODS) return;
    int n = i >> 3, p = i & 7;
    float s = b_lin[p];
    const float* hrow = &g_Hcheb[(size_t)n*KH];
    const float* wrow = &W_lin[p*HID];
#pragma unroll
    for (int h = 0; h < HID; ++h) s += fmaxf(hrow[h], 0.f) * wrow[h];
    out[i] = s;
}

// ---------------- launch ----------------
extern "C" void kernel_launch(void* const* d_in, const int* in_sizes, int n_in,
                              void* d_out, int out_size)
{
    const float* timesteps  = (const float*)d_in[0];
    const int*   edge_index = (const int*)  d_in[1];
    const float* Wx         = (const float*)d_in[2];
    const float* Wh         = (const float*)d_in[3];
    const float* w_c        = (const float*)d_in[4];
    const float* b_gates    = (const float*)d_in[5];
    const float* W_lin      = (const float*)d_in[6];
    const float* b_lin      = (const float*)d_in[7];
    float* out = (float*)d_out;

    cudaFuncSetAttribute(lstm_step_kernel,
                         cudaFuncAttributeMaxDynamicSharedMemorySize, SMEM_BYTES);

    void* p;
    cudaGetSymbolAddress(&p, g_XT);    float* XT    = (float*)p;
    cudaGetSymbolAddress(&p, g_Hcheb); float* Hcheb = (float*)p;

    init_kernel          <<<(N_NODES*KH + 255)/256, 256>>>(timesteps, Wx, Wh);
    edge_deg_count_kernel<<<(N_EDGES + 255)/256, 256>>>(edge_index);
    scan_part_kernel     <<<SCAN_BLK, 1024>>>();
    scan_fix_kernel      <<<SCAN_BLK, 1024>>>();
    scatter_edges_kernel <<<(N_EDGES + 255)/256, 256>>>(edge_index);

    const size_t plane = (size_t)N_NODES*TF;
    dim3 chebGrid2((N_NODES + 7)/8, 2);   // C=64 (all timesteps batched)
    dim3 chebGrid1((N_NODES + 7)/8, 1);   // C=32

    // Chebyshev planes of the inputs: T1..T4 over [N, 64]
    for (int k = 1; k < KCHEB; ++k) {
        cheb_step_kernel<<<chebGrid2, 256>>>(
            XT + (size_t)(k-1)*plane,
            (k >= 2) ? XT + (size_t)(k-2)*plane : nullptr,
            XT + (size_t)k*plane,
            TF, (k == 1) ? 1.f : 2.f);
    }

    const int nblk = (N_NODES + NODES_PER_BLK - 1)/NODES_PER_BLK;
    for (int t = 0; t < T_STEPS; ++t) {
        if (t > 0) {  // t==0: H=0 -> all hidden cheb planes stay 0 (zeroed in init)
            for (int k = 1; k < KCHEB; ++k) {
                cheb_step_kernel<<<chebGrid1, 256>>>(
                    Hcheb + 32*(k-1),
                    (k >= 2) ? Hcheb + 32*(k-2) : nullptr,
                    Hcheb + 32*k,
                    KH, (k == 1) ? 1.f : 2.f);
            }
        }
        lstm_step_kernel<<<nblk, 256, SMEM_BYTES>>>(w_c, b_gates, t, (t == 0) ? KH : 0);
    }

    final_out_kernel<<<(N_NODES*PERIODS + 255)/256, 256>>>(W_lin, b_lin, out);
}

// round 15
// speedup vs baseline: 1.2816x; 1.0676x over previous
#include <cuda_runtime.h>
#include <cuda_fp16.h>
#include <cstdint>

// ---------------- problem constants ----------------
#define N_NODES 30000
#define N_EDGES 480000
#define T_STEPS 8
#define F_IN    8
#define HID     32
#define KCHEB   5
#define PERIODS 8

#define KH   (KCHEB*HID)    // 160 hidden-cheb columns
#define KX   (KCHEB*F_IN)   // 40 input-cheb columns
#define KTOT (KH+KX)        // 200
#define GATES 128           // 4*HID
#define TF   (T_STEPS*F_IN) // 64

#define NODES_PER_BLK 128
#define AT_STR 132          // transposed A stride in floats (128 nodes + pad, %4==0 for LDS.128)
#define GSTR   130          // gate buffer stride (even -> 8B-aligned ull stores)
#define SMEM_BYTES ((KTOT*GATES + KTOT*AT_STR)*4)   // 208000 B

#define SCAN_BLK 30         // ceil(30000/1024)

// ---------------- device scratch (static, allocation-free) ----------------
__device__ int    g_deg[N_NODES];
__device__ int    g_counts[N_NODES];
__device__ int    g_cursor[N_NODES];
__device__ float  g_dis[N_NODES];
__device__ int    g_rowptr[N_NODES+1];
__device__ int    g_partials[SCAN_BLK];
__device__ int2   g_edge[N_EDGES];                  // (src, val-as-int) fused
__device__ __half g_XT[(size_t)KCHEB*N_NODES*TF];   // cheb planes of inputs (fp16), [k][n][t*8+f]
__device__ __half g_Hcheb[(size_t)N_NODES*KH];      // fp16 [n][k*32+h]; cols 0:32 hold H
__device__ float  g_C[(size_t)N_NODES*HID];
__device__ float  g_Wcat[KTOT*GATES];               // flattened [200][128] gate weights

// ---------------- helpers ----------------
__device__ __forceinline__ float sigmoidf_(float x){ return 1.f/(1.f+__expf(-x)); }
__device__ __forceinline__ float tanhf_(float x){ return 2.f/(1.f+__expf(-2.f*x)) - 1.f; }

__device__ __forceinline__ float2 h2f(unsigned int u){
    __half2 h = *reinterpret_cast<__half2*>(&u);
    return __half22float2(h);
}

__device__ __forceinline__ unsigned long long bcast2(float a){
    unsigned long long r;
    asm("mov.b64 %0, {%1, %1};" : "=l"(r) : "r"(__float_as_uint(a)));
    return r;
}
__device__ __forceinline__ void fma2(unsigned long long &d, unsigned long long a, unsigned long long b){
    asm("fma.rn.f32x2 %0, %1, %2, %0;" : "+l"(d) : "l"(a), "l"(b));
}

// ---------------- fused setup: zero + weight flatten + input transpose ----------------
__global__ void init_kernel(const float* __restrict__ ts,
                            const float* __restrict__ Wx, const float* __restrict__ Wh){
    int i = blockIdx.x*blockDim.x + threadIdx.x;
    if (i < N_NODES) { g_deg[i] = 0; g_counts[i] = 0; g_cursor[i] = 0; }
    if (i < N_NODES*HID) g_C[i] = 0.f;
    if (i < N_NODES*KH) g_Hcheb[i] = __float2half(0.f);   // all 5 cheb planes of H zeroed
    if (i < KTOT*GATES) {
        int row = i / GATES, colc = i - row*GATES;
        int g = colc >> 5, h = colc & 31;
        float v;
        if (row < KH) {
            int k = row >> 5, ii = row & 31;
            v = Wh[((g*KCHEB + k)*HID + ii)*HID + h];
        } else {
            int r = row - KH;
            int k = r >> 3, f = r & 7;
            v = Wx[((g*KCHEB + k)*F_IN + f)*HID + h];
        }
        g_Wcat[i] = v;
    }
    if (i < N_NODES*TF) {
        int n = i / TF, r = i - n*TF;
        int t = r >> 3, f = r & 7;
        g_XT[i] = __float2half_rn(ts[((size_t)t*N_NODES + n)*F_IN + f]);
    }
}

__global__ void edge_deg_count_kernel(const int* __restrict__ ei){
    int e = blockIdx.x*blockDim.x + threadIdx.x;
    if (e >= N_EDGES) return;
    int s = ei[e], d = ei[N_EDGES + e];
    if (s != d) atomicAdd(&g_deg[s], 1);
    atomicAdd(&g_counts[d], 1);
}

// multi-block scan phase 1: per-block exclusive scan + block total; also computes dis
__global__ void scan_part_kernel(){
    __shared__ int wsum[32];
    int b = blockIdx.x, t = threadIdx.x;
    int lane = t & 31, wid = t >> 5;
    int i = b*1024 + t;
    if (i < N_NODES) {
        int d = g_deg[i];
        g_dis[i] = (d > 0) ? rsqrtf((float)d) : 0.f;
    }
    int v = (i < N_NODES) ? g_counts[i] : 0;
    int x = v;
#pragma unroll
    for (int off = 1; off < 32; off <<= 1) {
        int y = __shfl_up_sync(0xffffffffu, x, off);
        if (lane >= off) x += y;
    }
    if (lane == 31) wsum[wid] = x;
    __syncthreads();
    if (wid == 0) {
        int s = wsum[lane];
#pragma unroll
        for (int off = 1; off < 32; off <<= 1) {
            int y = __shfl_up_sync(0xffffffffu, s, off);
            if (lane >= off) s += y;
        }
        wsum[lane] = s;
    }
    __syncthreads();
    int pre = (wid > 0) ? wsum[wid-1] : 0;
    if (i < N_NODES) g_rowptr[i] = pre + x - v;      // block-local exclusive
    if (t == 1023) g_partials[b] = pre + x;          // block total (inclusive)
}

// phase 2: add cross-block offsets
__global__ void scan_fix_kernel(){
    __shared__ int s_off;
    int b = blockIdx.x, t = threadIdx.x;
    if (t == 0) {
        int s = 0;
        for (int j = 0; j < b; ++j) s += g_partials[j];
        s_off = s;
    }
    __syncthreads();
    int i = b*1024 + t;
    if (i < N_NODES) g_rowptr[i] += s_off;
    if (b == SCAN_BLK-1 && t == 0) g_rowptr[N_NODES] = s_off + g_partials[b];
}

__global__ void scatter_edges_kernel(const int* __restrict__ ei){
    int e = blockIdx.x*blockDim.x + threadIdx.x;
    if (e >= N_EDGES) return;
    int s = ei[e], d = ei[N_EDGES + e];
    int pos = g_rowptr[d] + atomicAdd(&g_cursor[d], 1);
    float v = (s == d) ? 0.f : -g_dis[s]*g_dis[d];   // minus of lap folded in
    g_edge[pos] = make_int2(s, __float_as_int(v));
}

// ---------------- Chebyshev step: out = a * Lhat(in) - sub  (fp16 data, fp32 accum) ----
// warp per node, lane per channel; grid.y selects 32-channel segment.
// Manually unrolled x8 to maximize gather MLP (L2-latency hiding).
__global__ void __launch_bounds__(256) cheb_step_kernel(
    const __half* __restrict__ in, const __half* __restrict__ sub,
    __half* __restrict__ out, int stride, float a)
{
    int node = (blockIdx.x * blockDim.x + threadIdx.x) >> 5;
    if (node >= N_NODES) return;
    int c = (blockIdx.y << 5) + (threadIdx.x & 31);
    int beg = g_rowptr[node], end = g_rowptr[node+1];
    float acc = 0.f;
    int e = beg;
    for (; e + 8 <= end; e += 8) {
        int2 e0 = __ldg(&g_edge[e  ]), e1 = __ldg(&g_edge[e+1]);
        int2 e2 = __ldg(&g_edge[e+2]), e3 = __ldg(&g_edge[e+3]);
        int2 e4 = __ldg(&g_edge[e+4]), e5 = __ldg(&g_edge[e+5]);
        int2 e6 = __ldg(&g_edge[e+6]), e7 = __ldg(&g_edge[e+7]);
        float x0 = __half2float(__ldg(&in[e0.x*stride + c]));
        float x1 = __half2float(__ldg(&in[e1.x*stride + c]));
        float x2 = __half2float(__ldg(&in[e2.x*stride + c]));
        float x3 = __half2float(__ldg(&in[e3.x*stride + c]));
        float x4 = __half2float(__ldg(&in[e4.x*stride + c]));
        float x5 = __half2float(__ldg(&in[e5.x*stride + c]));
        float x6 = __half2float(__ldg(&in[e6.x*stride + c]));
        float x7 = __half2float(__ldg(&in[e7.x*stride + c]));
        acc += __int_as_float(e0.y)*x0; acc += __int_as_float(e1.y)*x1;
        acc += __int_as_float(e2.y)*x2; acc += __int_as_float(e3.y)*x3;
        acc += __int_as_float(e4.y)*x4; acc += __int_as_float(e5.y)*x5;
        acc += __int_as_float(e6.y)*x6; acc += __int_as_float(e7.y)*x7;
    }
    if (e + 4 <= end) {
        int2 e0 = __ldg(&g_edge[e  ]), e1 = __ldg(&g_edge[e+1]);
        int2 e2 = __ldg(&g_edge[e+2]), e3 = __ldg(&g_edge[e+3]);
        float x0 = __half2float(__ldg(&in[e0.x*stride + c]));
        float x1 = __half2float(__ldg(&in[e1.x*stride + c]));
        float x2 = __half2float(__ldg(&in[e2.x*stride + c]));
        float x3 = __half2float(__ldg(&in[e3.x*stride + c]));
        acc += __int_as_float(e0.y)*x0; acc += __int_as_float(e1.y)*x1;
        acc += __int_as_float(e2.y)*x2; acc += __int_as_float(e3.y)*x3;
        e += 4;
    }
    if (e + 2 <= end) {
        int2 e0 = __ldg(&g_edge[e]), e1 = __ldg(&g_edge[e+1]);
        float x0 = __half2float(__ldg(&in[e0.x*stride + c]));
        float x1 = __half2float(__ldg(&in[e1.x*stride + c]));
        acc += __int_as_float(e0.y)*x0; acc += __int_as_float(e1.y)*x1;
        e += 2;
    }
    if (e < end) {
        int2 e0 = __ldg(&g_edge[e]);
        acc += __int_as_float(e0.y)*__half2float(__ldg(&in[e0.x*stride + c]));
    }

    int idx = node*stride + c;
    float r = a * acc;
    if (sub) r -= __half2float(sub[idx]);
    out[idx] = __float2half_rn(r);
}

// ---------------- fused gate GEMM [128,200]x[200,128] + LSTM pointwise ----------------
// Outer-product register tiling: 256 threads = 16 node-groups x 16 gate-groups,
// each thread computes an 8x8 tile (as 8x4 f32x2 accumulators).
// A is staged TRANSPOSED in smem (fp32): At[kk][node]; sources are fp16.
// kbeg: first K column (t==0 -> KH, hidden cheb planes are all zero).
__global__ void __launch_bounds__(256, 1) lstm_step_kernel(
    const float* __restrict__ w_c, const float* __restrict__ b_gates, int t, int kbeg)
{
    extern __shared__ float sm[];
    float* Wsm = sm;                     // [KTOT][128]
    float* At  = sm + KTOT*GATES;        // [KTOT][AT_STR]
    int tid = threadIdx.x;
    int nodeBase = blockIdx.x * NODES_PER_BLK;

    // stage weights (rows kbeg..KTOT)
    for (int i = kbeg*GATES + tid; i < KTOT*GATES; i += 256) Wsm[i] = g_Wcat[i];

    // stage hidden cheb part of At (transposed): fp16 source, uint4 = 8 halves
    // uint4 lanes: v.x = halves 0,1 | v.y = 2,3 | v.z = 4,5 | v.w = 6,7
    if (kbeg == 0) {
        int nl = tid >> 1, hf = tid & 1;
        int node = nodeBase + nl;
        bool ok = node < N_NODES;
        const uint4* src = (const uint4*)(g_Hcheb + (size_t)node*KH + hf*(KH/2));
#pragma unroll
        for (int q = 0; q < KH/16; ++q) {          // 10 uint4 per half-row
            uint4 v = ok ? __ldg(&src[q]) : make_uint4(0u,0u,0u,0u);
            int kk = hf*(KH/2) + q*8;
            float2 p0 = h2f(v.x), p1 = h2f(v.y), p2 = h2f(v.z), p3 = h2f(v.w);
            At[(kk+0)*AT_STR + nl] = p0.x; At[(kk+1)*AT_STR + nl] = p0.y;
            At[(kk+2)*AT_STR + nl] = p1.x; At[(kk+3)*AT_STR + nl] = p1.y;
            At[(kk+4)*AT_STR + nl] = p2.x; At[(kk+5)*AT_STR + nl] = p2.y;
            At[(kk+6)*AT_STR + nl] = p3.x; At[(kk+7)*AT_STR + nl] = p3.y;
        }
    }
    // stage input cheb part of At (transposed): per (node, k) one uint4 = 8 halves
    {
        const size_t plane = (size_t)N_NODES*TF;
        for (int i = tid; i < NODES_PER_BLK*KCHEB; i += 256) {
            int nl = i / KCHEB, k = i - nl*KCHEB;
            int node = nodeBase + nl;
            uint4 v = (node < N_NODES)
                ? __ldg((const uint4*)(g_XT + (size_t)k*plane + (size_t)node*TF + t*F_IN))
                : make_uint4(0u,0u,0u,0u);
            int kk = KH + k*F_IN;
            float2 p0 = h2f(v.x), p1 = h2f(v.y), p2 = h2f(v.z), p3 = h2f(v.w);
            At[(kk+0)*AT_STR + nl] = p0.x; At[(kk+1)*AT_STR + nl] = p0.y;
            At[(kk+2)*AT_STR + nl] = p1.x; At[(kk+3)*AT_STR + nl] = p1.y;
            At[(kk+4)*AT_STR + nl] = p2.x; At[(kk+5)*AT_STR + nl] = p2.y;
            At[(kk+6)*AT_STR + nl] = p3.x; At[(kk+7)*AT_STR + nl] = p3.y;
        }
    }
    __syncthreads();

    int jg = tid & 15;      // gate group: gates 8*jg .. 8*jg+7
    int ig = tid >> 4;      // node group: nodes 8*ig .. 8*ig+7
    unsigned long long acc[8][4];
#pragma unroll
    for (int m = 0; m < 8; ++m)
#pragma unroll
        for (int c = 0; c < 4; ++c) acc[m][c] = 0ull;

    const float* abase = &At[ig*8];
    const float* wbase = &Wsm[jg*8];
#pragma unroll 2
    for (int kk = kbeg; kk < KTOT; ++kk) {
        float4 a0 = *(const float4*)&abase[kk*AT_STR];
        float4 a1 = *(const float4*)&abase[kk*AT_STR + 4];
        ulonglong2 w0 = *(const ulonglong2*)&wbase[kk*GATES];
        ulonglong2 w1 = *(const ulonglong2*)&wbase[kk*GATES + 4];
        unsigned long long A0 = bcast2(a0.x), A1 = bcast2(a0.y);
        unsigned long long A2 = bcast2(a0.z), A3 = bcast2(a0.w);
        unsigned long long A4 = bcast2(a1.x), A5 = bcast2(a1.y);
        unsigned long long A6 = bcast2(a1.z), A7 = bcast2(a1.w);
        fma2(acc[0][0],A0,w0.x); fma2(acc[0][1],A0,w0.y); fma2(acc[0][2],A0,w1.x); fma2(acc[0][3],A0,w1.y);
        fma2(acc[1][0],A1,w0.x); fma2(acc[1][1],A1,w0.y); fma2(acc[1][2],A1,w1.x); fma2(acc[1][3],A1,w1.y);
        fma2(acc[2][0],A2,w0.x); fma2(acc[2][1],A2,w0.y); fma2(acc[2][2],A2,w1.x); fma2(acc[2][3],A2,w1.y);
        fma2(acc[3][0],A3,w0.x); fma2(acc[3][1],A3,w0.y); fma2(acc[3][2],A3,w1.x); fma2(acc[3][3],A3,w1.y);
        fma2(acc[4][0],A4,w0.x); fma2(acc[4][1],A4,w0.y); fma2(acc[4][2],A4,w1.x); fma2(acc[4][3],A4,w1.y);
        fma2(acc[5][0],A5,w0.x); fma2(acc[5][1],A5,w0.y); fma2(acc[5][2],A5,w1.x); fma2(acc[5][3],A5,w1.y);
        fma2(acc[6][0],A6,w0.x); fma2(acc[6][1],A6,w0.y); fma2(acc[6][2],A6,w1.x); fma2(acc[6][3],A6,w1.y);
        fma2(acc[7][0],A7,w0.x); fma2(acc[7][1],A7,w0.y); fma2(acc[7][2],A7,w1.x); fma2(acc[7][3],A7,w1.y);
    }
    __syncthreads();            // At free; reuse as gate buffer (stride GSTR)
    float* Gsm = At;
#pragma unroll
    for (int m = 0; m < 8; ++m) {
        int row = (ig*8 + m)*GSTR + jg*8;
#pragma unroll
        for (int c = 0; c < 4; ++c)
            *(unsigned long long*)&Gsm[row + 2*c] = acc[m][c];
    }
    __syncthreads();

    for (int idx = tid; idx < NODES_PER_BLK*HID; idx += 256) {
        int nl2 = idx >> 5, h = idx & 31;
        int node = nodeBase + nl2;
        if (node >= N_NODES) continue;
        float Cold = g_C[(size_t)node*HID + h];
        const float* grow = &Gsm[nl2*GSTR];
        float gi = grow[h]      + w_c[h]      * Cold + b_gates[h];
        float gf = grow[32 + h] + w_c[32 + h] * Cold + b_gates[32 + h];
        float gc = grow[64 + h]                      + b_gates[64 + h];
        float go = grow[96 + h]                      + b_gates[96 + h];
        float I  = sigmoidf_(gi);
        float F  = sigmoidf_(gf);
        float Tg = tanhf_(gc);
        float Cn = F * Cold + I * Tg;
        float O  = sigmoidf_(go + w_c[64 + h] * Cn);
        g_C[(size_t)node*HID + h] = Cn;
        g_Hcheb[(size_t)node*KH + h] = __float2half_rn(O * tanhf_(Cn));  // new H into cheb col 0
    }
}

// ---------------- final: out = relu(H) @ W_lin^T + b_lin ----------------
__global__ void final_out_kernel(const float* __restrict__ W_lin, const float* __restrict__ b_lin,
                                 float* __restrict__ out)
{
    int i = blockIdx.x*blockDim.x + threadIdx.x;
    if (i >= N_NODES*PERIODS) return;
    int n = i >> 3, p = i & 7;
    float s = b_lin[p];
    const __half* hrow = &g_Hcheb[(size_t)n*KH];
    const float* wrow = &W_lin[p*HID];
#pragma unroll
    for (int h = 0; h < HID; ++h) s += fmaxf(__half2float(hrow[h]), 0.f) * wrow[h];
    out[i] = s;
}

// ---------------- launch ----------------
extern "C" void kernel_launch(void* const* d_in, const int* in_sizes, int n_in,
                              void* d_out, int out_size)
{
    const float* timesteps  = (const float*)d_in[0];
    const int*   edge_index = (const int*)  d_in[1];
    const float* Wx         = (const float*)d_in[2];
    const float* Wh         = (const float*)d_in[3];
    const float* w_c        = (const float*)d_in[4];
    const float* b_gates    = (const float*)d_in[5];
    const float* W_lin      = (const float*)d_in[6];
    const float* b_lin      = (const float*)d_in[7];
    float* out = (float*)d_out;

    cudaFuncSetAttribute(lstm_step_kernel,
                         cudaFuncAttributeMaxDynamicSharedMemorySize, SMEM_BYTES);

    void* p;
    cudaGetSymbolAddress(&p, g_XT);    __half* XT    = (__half*)p;
    cudaGetSymbolAddress(&p, g_Hcheb); __half* Hcheb = (__half*)p;

    init_kernel          <<<(N_NODES*KH + 255)/256, 256>>>(timesteps, Wx, Wh);
    edge_deg_count_kernel<<<(N_EDGES + 255)/256, 256>>>(edge_index);
    scan_part_kernel     <<<SCAN_BLK, 1024>>>();
    scan_fix_kernel      <<<SCAN_BLK, 1024>>>();
    scatter_edges_kernel <<<(N_EDGES + 255)/256, 256>>>(edge_index);

    const size_t plane = (size_t)N_NODES*TF;
    dim3 chebGrid2((N_NODES + 7)/8, 2);   // C=64 (all timesteps batched)
    dim3 chebGrid1((N_NODES + 7)/8, 1);   // C=32

    // Chebyshev planes of the inputs: T1..T4 over [N, 64]
    for (int k = 1; k < KCHEB; ++k) {
        cheb_step_kernel<<<chebGrid2, 256>>>(
            XT + (size_t)(k-1)*plane,
            (k >= 2) ? XT + (size_t)(k-2)*plane : nullptr,
            XT + (size_t)k*plane,
            TF, (k == 1) ? 1.f : 2.f);
    }

    const int nblk = (N_NODES + NODES_PER_BLK - 1)/NODES_PER_BLK;
    for (int t = 0; t < T_STEPS; ++t) {
        if (t > 0) {  // t==0: H=0 -> all hidden cheb planes stay 0 (zeroed in init)
            for (int k = 1; k < KCHEB; ++k) {
                cheb_step_kernel<<<chebGrid1, 256>>>(
                    Hcheb + 32*(k-1),
                    (k >= 2) ? Hcheb + 32*(k-2) : nullptr,
                    Hcheb + 32*k,
                    KH, (k == 1) ? 1.f : 2.f);
            }
        }
        lstm_step_kernel<<<nblk, 256, SMEM_BYTES>>>(w_c, b_gates, t, (t == 0) ? KH : 0);
    }

    final_out_kernel<<<(N_NODES*PERIODS + 255)/256, 256>>>(W_lin, b_lin, out);
}